// round 4
// baseline (speedup 1.0000x reference)
#include <cuda_runtime.h>
#include <cstdint>

// Fused single-kernel two-reduction over 8M points (f32x2 packed math):
//   g   = sum_i exp(-0.5*((|p_i - cam|-2)/4)^2) / (4*sqrt(2*pi))
//   cnt = # points strictly inside rotated+translated CCW triangle
// out[0] = 1/(g+eps) + 1/(cnt+eps)

#define BLOCKS  592
#define THREADS 256
#define UNROLL  6

__device__ float g_partial_gauss[BLOCKS];
__device__ float g_partial_count[BLOCKS];
__device__ int   g_ticket = 0;   // reset by finalizing block each call

#define GAUSS_NORM 0.09973557010f   // 1 / (4 * sqrt(2*pi))
#define EPSV 1e-06f
// exp(-0.5*((d-2)/4)^2) = ex2(-(K*d - 2K)^2), K = sqrt(0.5*log2(e))/4
#define KFOLD  0.2123346587f
#define KFOLD2 0.4246693174f        // 2*K

// ---- scalar fast-math ----
__device__ __forceinline__ float fast_sqrt(float x) {
    float r; asm("sqrt.approx.f32 %0, %1;" : "=f"(r) : "f"(x)); return r;
}
__device__ __forceinline__ float fast_ex2(float x) {
    float r; asm("ex2.approx.f32 %0, %1;" : "=f"(r) : "f"(x)); return r;
}

// ---- packed f32x2 (Blackwell) ----
__device__ __forceinline__ uint64_t pk2(float lo, float hi) {
    uint64_t r; asm("mov.b64 %0, {%1, %2};" : "=l"(r) : "f"(lo), "f"(hi)); return r;
}
__device__ __forceinline__ uint64_t fma2(uint64_t a, uint64_t b, uint64_t c) {
    uint64_t r; asm("fma.rn.f32x2 %0, %1, %2, %3;" : "=l"(r) : "l"(a), "l"(b), "l"(c)); return r;
}
__device__ __forceinline__ uint64_t add2(uint64_t a, uint64_t b) {
    uint64_t r; asm("add.rn.f32x2 %0, %1, %2;" : "=l"(r) : "l"(a), "l"(b)); return r;
}
__device__ __forceinline__ uint64_t mul2(uint64_t a, uint64_t b) {
    uint64_t r; asm("mul.rn.f32x2 %0, %1, %2;" : "=l"(r) : "l"(a), "l"(b)); return r;
}
__device__ __forceinline__ float lo32f(uint64_t v) { return __uint_as_float((uint32_t)v); }
__device__ __forceinline__ float hi32f(uint64_t v) { return __uint_as_float((uint32_t)(v >> 32)); }

struct GeoP {
    uint64_t ncx, ncy;                 // (-cx,-cx), (-cy,-cy)
    uint64_t a0, b0, d0, a1, b1, d1;   // packed edge-affine coeffs
    uint64_t S, m1;                    // (d0+d1+d2) pack, (-1,-1)
    float scx, scy;                    // scalar camera (tail path)
    float sa0, sb0, sd0, sa1, sb1, sd1, sa2, sb2, sd2;
};

// packed body: one float4 = two points
__device__ __forceinline__ void body2(const float4 q, const GeoP& G,
                                      float& ag0, float& ag1, int& acc_c)
{
    const uint64_t pxp = pk2(q.x, q.z);
    const uint64_t pyp = pk2(q.y, q.w);

    // gaussian
    uint64_t dxp = add2(pxp, G.ncx);
    uint64_t dyp = add2(pyp, G.ncy);
    uint64_t r2p = fma2(dxp, dxp, mul2(dyp, dyp));
    float da = fast_sqrt(lo32f(r2p));
    float db = fast_sqrt(hi32f(r2p));
    float wa = fmaf(da, KFOLD, -KFOLD2);
    float wb = fmaf(db, KFOLD, -KFOLD2);
    ag0 += fast_ex2(-wa * wa);
    ag1 += fast_ex2(-wb * wb);

    // crosses: c2 = S - c0 - c1 (closed polygon: edge normals sum to 0)
    uint64_t c0p = fma2(G.a0, pxp, fma2(G.b0, pyp, G.d0));
    uint64_t c1p = fma2(G.a1, pxp, fma2(G.b1, pyp, G.d1));
    uint64_t c2p = fma2(add2(c0p, c1p), G.m1, G.S);

    // inside <=> all signs clear; n = ~(c0|c1|c2) has sign bit 1 iff inside
    uint32_t n0 = ~((uint32_t)c0p | (uint32_t)c1p | (uint32_t)c2p);
    uint32_t n1 = ~((uint32_t)(c0p >> 32) | (uint32_t)(c1p >> 32) | (uint32_t)(c2p >> 32));
    acc_c += (int)(n0 >> 31) + (int)(n1 >> 31);
}

__device__ __forceinline__ void body1(const float px, const float py,
                                      const GeoP& G, float& ag, int& acc_c)
{
    float dx = px - G.scx, dy = py - G.scy;
    float d  = fast_sqrt(fmaf(dx, dx, dy * dy));
    float w  = fmaf(d, KFOLD, -KFOLD2);
    ag += fast_ex2(-w * w);
    float c0 = fmaf(G.sa0, px, fmaf(G.sb0, py, G.sd0));
    float c1 = fmaf(G.sa1, px, fmaf(G.sb1, py, G.sd1));
    float c2 = fmaf(G.sa2, px, fmaf(G.sb2, py, G.sd2));
    if (c0 > 0.f && c1 > 0.f && c2 > 0.f) acc_c += 1;
}

__global__ __launch_bounds__(THREADS, 4)
void fused_kernel(const float4* __restrict__ pts4, int n4,
                  const float* __restrict__ cam, int odd_point,
                  const float* __restrict__ pts_scalar,
                  float* __restrict__ out)
{
    // ---- uniform geometry setup ----
    GeoP G;
    const float cx = cam[0], cy = cam[1], yaw = cam[2];
    float s, c;
    __sincosf(yaw, &s, &c);
    // POLY {(0,0),(2,7),(-2,7)} is CCW; rotation preserves orientation.
    const float v0x = cx,                  v0y = cy;
    const float v1x =  2.f*c - 7.f*s + cx, v1y =  2.f*s + 7.f*c + cy;
    const float v2x = -2.f*c - 7.f*s + cx, v2y = -2.f*s + 7.f*c + cy;
    // cross_k(p) = a_k*px + b_k*py + d_k
    float ex = v1x - v0x, ey = v1y - v0y;
    G.sa0 = -ey; G.sb0 = ex; G.sd0 = ey * v0x - ex * v0y;
    ex = v2x - v1x; ey = v2y - v1y;
    G.sa1 = -ey; G.sb1 = ex; G.sd1 = ey * v1x - ex * v1y;
    ex = v0x - v2x; ey = v0y - v2y;
    G.sa2 = -ey; G.sb2 = ex; G.sd2 = ey * v2x - ex * v2y;
    G.scx = cx; G.scy = cy;

    G.ncx = pk2(-cx, -cx);  G.ncy = pk2(-cy, -cy);
    G.a0 = pk2(G.sa0, G.sa0); G.b0 = pk2(G.sb0, G.sb0); G.d0 = pk2(G.sd0, G.sd0);
    G.a1 = pk2(G.sa1, G.sa1); G.b1 = pk2(G.sb1, G.sb1); G.d1 = pk2(G.sd1, G.sd1);
    const float Ssum = G.sd0 + G.sd1 + G.sd2;   // a's and b's sum to 0
    G.S  = pk2(Ssum, Ssum);
    G.m1 = pk2(-1.0f, -1.0f);

    float ag0 = 0.f, ag1 = 0.f;
    int   acc_c = 0;

    // contiguous per-block chunks -> small immediate LDG offsets
    const int chunk   = THREADS * UNROLL;           // float4s per block-iter
    const int gstride = BLOCKS * chunk;
    const int nfull   = (n4 / chunk) * chunk;       // full-chunk region

    for (int base = blockIdx.x * chunk; base < nfull; base += gstride) {
        const float4* p = pts4 + base + threadIdx.x;
        float4 q[UNROLL];
        #pragma unroll
        for (int u = 0; u < UNROLL; u++) q[u] = p[u * THREADS];
        #pragma unroll
        for (int u = 0; u < UNROLL; u++) body2(q[u], G, ag0, ag1, acc_c);
    }
    // tail float4s
    for (int i = nfull + blockIdx.x * THREADS + threadIdx.x; i < n4;
         i += BLOCKS * THREADS) {
        body2(pts4[i], G, ag0, ag1, acc_c);
    }
    // lone trailing point if N odd
    if (odd_point && blockIdx.x == 0 && threadIdx.x == 0) {
        body1(pts_scalar[4 * n4], pts_scalar[4 * n4 + 1], G, ag0, acc_c);
    }

    float acc_g = (ag0 + ag1) * GAUSS_NORM;
    float acc_cf = (float)acc_c;

    // ---- block reduction (fixed tree -> deterministic) ----
    __shared__ float sg[THREADS];
    __shared__ float sc[THREADS];
    sg[threadIdx.x] = acc_g;
    sc[threadIdx.x] = acc_cf;
    __syncthreads();
    #pragma unroll
    for (int off = THREADS / 2; off > 0; off >>= 1) {
        if (threadIdx.x < off) {
            sg[threadIdx.x] += sg[threadIdx.x + off];
            sc[threadIdx.x] += sc[threadIdx.x + off];
        }
        __syncthreads();
    }

    __shared__ bool is_last;
    if (threadIdx.x == 0) {
        g_partial_gauss[blockIdx.x] = sg[0];
        g_partial_count[blockIdx.x] = sc[0];
        __threadfence();
        is_last = (atomicAdd(&g_ticket, 1) == BLOCKS - 1);
    }
    __syncthreads();

    if (is_last) {
        __threadfence();
        float agf = 0.f, acf = 0.f;
        for (int k = threadIdx.x; k < BLOCKS; k += THREADS) {
            agf += g_partial_gauss[k];
            acf += g_partial_count[k];
        }
        sg[threadIdx.x] = agf;
        sc[threadIdx.x] = acf;
        __syncthreads();
        #pragma unroll
        for (int off = THREADS / 2; off > 0; off >>= 1) {
            if (threadIdx.x < off) {
                sg[threadIdx.x] += sg[threadIdx.x + off];
                sc[threadIdx.x] += sc[threadIdx.x + off];
            }
            __syncthreads();
        }
        if (threadIdx.x == 0) {
            out[0] = 1.0f / (sg[0] + EPSV) + 1.0f / (sc[0] + EPSV);
            g_ticket = 0;   // re-arm for graph replay
        }
    }
}

extern "C" void kernel_launch(void* const* d_in, const int* in_sizes, int n_in,
                              void* d_out, int out_size)
{
    const float* points = (const float*)d_in[0];   // [N,2] float32
    const float* cam    = (const float*)d_in[1];   // [3]  float32
    float* out = (float*)d_out;

    int n_floats  = in_sizes[0];          // 2*N
    int n4        = n_floats / 4;         // float4 groups (2 points each)
    int odd_point = ((n_floats / 2) & 1); // lone trailing point if N odd

    fused_kernel<<<BLOCKS, THREADS>>>((const float4*)points, n4, cam,
                                      odd_point, points, out);
}

// round 5
// speedup vs baseline: 1.0019x; 1.0019x over previous
#include <cuda_runtime.h>
#include <cstdint>

// Fused single-kernel two-reduction over 8M points:
//   g   = sum_i exp(-0.5*((|p_i - cam|-2)/4)^2) / (4*sqrt(2*pi))
//   cnt = # points strictly inside rotated+translated CCW triangle
// out[0] = 1/(g+eps) + 1/(cnt+eps)
// Count is computed as N - (# outside), via sign-bit OR of the three crosses.

#define BLOCKS  888          // 6 CTAs/SM * 148 SMs, one exact wave
#define THREADS 256
#define UNROLL  4

__device__ float g_partial_gauss[BLOCKS];
__device__ float g_partial_out[BLOCKS];
__device__ int   g_ticket = 0;   // reset by finalizing block each call

#define GAUSS_NORM 0.09973557010f   // 1 / (4 * sqrt(2*pi))
#define EPSV 1e-06f
// exp(-0.5*((d-2)/4)^2) = ex2(-(K*d - 2K)^2), K = sqrt(0.5*log2(e))/4
#define KFOLD  0.2123346587f
#define KFOLD2 0.4246693174f        // 2*K

__device__ __forceinline__ float fast_sqrt(float x) {
    float r; asm("sqrt.approx.f32 %0, %1;" : "=f"(r) : "f"(x)); return r;
}
__device__ __forceinline__ float fast_ex2(float x) {
    float r; asm("ex2.approx.f32 %0, %1;" : "=f"(r) : "f"(x)); return r;
}

struct Geo {
    float cx, cy;
    float a0, b0, d0, a1, b1, d1, a2, b2, d2;  // cross_k(p) = a*px + b*py + d
};

__device__ __forceinline__ void body(const float px, const float py,
                                     const Geo& G, float& acc_g, int& acc_out)
{
    // gaussian
    float dx = px - G.cx, dy = py - G.cy;
    float d  = fast_sqrt(fmaf(dx, dx, dy * dy));
    float w  = fmaf(d, KFOLD, -KFOLD2);          // K*(d-2)
    acc_g += fast_ex2(-w * w);

    // crosses; CCW triangle => inside <=> all > 0; count OUTSIDE via sign bits
    float c0 = fmaf(G.a0, px, fmaf(G.b0, py, G.d0));
    float c1 = fmaf(G.a1, px, fmaf(G.b1, py, G.d1));
    float c2 = fmaf(G.a2, px, fmaf(G.b2, py, G.d2));
    uint32_t u = __float_as_uint(c0) | __float_as_uint(c1) | __float_as_uint(c2);
    acc_out += (int)(u >> 31);
}

__global__ __launch_bounds__(THREADS, 6)
void fused_kernel(const float4* __restrict__ pts4, int n4,
                  const float* __restrict__ cam, int odd_point,
                  const float* __restrict__ pts_scalar,
                  float n_points,
                  float* __restrict__ out)
{
    // ---- uniform geometry setup ----
    Geo G;
    G.cx = cam[0]; G.cy = cam[1];
    const float yaw = cam[2];
    float s, c;
    __sincosf(yaw, &s, &c);
    // POLY {(0,0),(2,7),(-2,7)} is CCW; rotation preserves orientation,
    // so all-negative is impossible (c0+c1+c2 = 2*area > 0).
    const float v0x = G.cx,                      v0y = G.cy;
    const float v1x =  2.f*c - 7.f*s + G.cx,     v1y =  2.f*s + 7.f*c + G.cy;
    const float v2x = -2.f*c - 7.f*s + G.cx,     v2y = -2.f*s + 7.f*c + G.cy;
    {
        float ex = v1x - v0x, ey = v1y - v0y;
        G.a0 = -ey; G.b0 = ex; G.d0 = ey * v0x - ex * v0y;
        ex = v2x - v1x; ey = v2y - v1y;
        G.a1 = -ey; G.b1 = ex; G.d1 = ey * v1x - ex * v1y;
        ex = v0x - v2x; ey = v0y - v2y;
        G.a2 = -ey; G.b2 = ex; G.d2 = ey * v2x - ex * v2y;
    }

    float acc_g0 = 0.f, acc_g1 = 0.f;
    int   acc_out = 0;

    const int stride  = BLOCKS * THREADS;
    const int tid0    = blockIdx.x * THREADS + threadIdx.x;
    const int strideU = UNROLL * stride;

    int i = tid0;
    for (; i + (UNROLL - 1) * stride < n4; i += strideU) {
        float4 q[UNROLL];
        #pragma unroll
        for (int u = 0; u < UNROLL; u++) q[u] = pts4[i + u * stride];
        #pragma unroll
        for (int u = 0; u < UNROLL; u++) {
            body(q[u].x, q[u].y, G, acc_g0, acc_out);
            body(q[u].z, q[u].w, G, acc_g1, acc_out);
        }
    }
    for (; i < n4; i += stride) {
        float4 q = pts4[i];
        body(q.x, q.y, G, acc_g0, acc_out);
        body(q.z, q.w, G, acc_g1, acc_out);
    }
    // lone trailing point if N odd
    if (odd_point && blockIdx.x == 0 && threadIdx.x == 0) {
        body(pts_scalar[4 * n4], pts_scalar[4 * n4 + 1], G, acc_g0, acc_out);
    }

    float acc_g = (acc_g0 + acc_g1) * GAUSS_NORM;
    float acc_o = (float)acc_out;

    // ---- block reduction (fixed tree -> deterministic) ----
    __shared__ float sg[THREADS];
    __shared__ float so[THREADS];
    sg[threadIdx.x] = acc_g;
    so[threadIdx.x] = acc_o;
    __syncthreads();
    #pragma unroll
    for (int off = THREADS / 2; off > 0; off >>= 1) {
        if (threadIdx.x < off) {
            sg[threadIdx.x] += sg[threadIdx.x + off];
            so[threadIdx.x] += so[threadIdx.x + off];
        }
        __syncthreads();
    }

    __shared__ bool is_last;
    if (threadIdx.x == 0) {
        g_partial_gauss[blockIdx.x] = sg[0];
        g_partial_out[blockIdx.x]   = so[0];
        __threadfence();
        is_last = (atomicAdd(&g_ticket, 1) == BLOCKS - 1);
    }
    __syncthreads();

    if (is_last) {
        __threadfence();
        float ag = 0.f, ao = 0.f;
        for (int k = threadIdx.x; k < BLOCKS; k += THREADS) {
            ag += g_partial_gauss[k];
            ao += g_partial_out[k];
        }
        sg[threadIdx.x] = ag;
        so[threadIdx.x] = ao;
        __syncthreads();
        #pragma unroll
        for (int off = THREADS / 2; off > 0; off >>= 1) {
            if (threadIdx.x < off) {
                sg[threadIdx.x] += sg[threadIdx.x + off];
                so[threadIdx.x] += so[threadIdx.x + off];
            }
            __syncthreads();
        }
        if (threadIdx.x == 0) {
            float inside = n_points - so[0];
            out[0] = 1.0f / (sg[0] + EPSV) + 1.0f / (inside + EPSV);
            g_ticket = 0;   // re-arm for graph replay
        }
    }
}

extern "C" void kernel_launch(void* const* d_in, const int* in_sizes, int n_in,
                              void* d_out, int out_size)
{
    const float* points = (const float*)d_in[0];   // [N,2] float32
    const float* cam    = (const float*)d_in[1];   // [3]  float32
    float* out = (float*)d_out;

    int n_floats  = in_sizes[0];          // 2*N
    int n4        = n_floats / 4;         // float4 groups (2 points each)
    int odd_point = ((n_floats / 2) & 1); // lone trailing point if N odd
    float n_points = (float)(n_floats / 2);

    fused_kernel<<<BLOCKS, THREADS>>>((const float4*)points, n4, cam,
                                      odd_point, points, n_points, out);
}